// round 16
// baseline (speedup 1.0000x reference)
#include <cuda_runtime.h>
#include <math.h>

#define NTHREADS 256
#define HSTRIDE 132   // padded stride for h1/h [48][132] (bank-conflict fix)
#define TSTRIDE 50    // padded stride for h_outT [64][50]

typedef unsigned long long u64;

__device__ __forceinline__ u64 pk2(float x, float y) {
    u64 r; asm("mov.b64 %0, {%1,%2};" : "=l"(r) : "f"(x), "f"(y)); return r;
}
__device__ __forceinline__ u64 bc2(float x) { return pk2(x, x); }
__device__ __forceinline__ u64 f2fma(u64 a, u64 b, u64 c) {
    u64 d; asm("fma.rn.f32x2 %0, %1, %2, %3;" : "=l"(d) : "l"(a), "l"(b), "l"(c)); return d;
}
__device__ __forceinline__ float2 up2(u64 v) {
    float lo, hi; asm("mov.b64 {%0,%1}, %2;" : "=f"(lo), "=f"(hi) : "l"(v));
    return make_float2(lo, hi);
}

__device__ __forceinline__ float lrelu(float x) { return x > 0.f ? x : 0.1f * x; }
__device__ __forceinline__ float fsig(float x) {
    return __fdividef(1.f, 1.f + __expf(-x));
}
__device__ __forceinline__ float ftanh(float x) {
    return 1.f - __fdividef(2.f, __expf(2.f * x) + 1.f);
}

__global__ __launch_bounds__(NTHREADS, 3) void policy_kernel(
    const int*   __restrict__ Nmat,   // [B,56] int32
    const float* __restrict__ adj,    // [B,3,48,48]
    const float* __restrict__ W1,  const float* __restrict__ b1,
    const float* __restrict__ W2,  const float* __restrict__ b2,
    const float* __restrict__ asW, const float* __restrict__ asb,
    const float* __restrict__ atW, const float* __restrict__ atb,
    const float* __restrict__ l1W, const float* __restrict__ l1b,
    const float* __restrict__ l2W, const float* __restrict__ l2b,
    const float* __restrict__ f1,  const float* __restrict__ f2,
    const float* __restrict__ s1,  const float* __restrict__ s2,
    const float* __restrict__ e1,  const float* __restrict__ e2,
    const float* __restrict__ t1W, const float* __restrict__ t1b,
    const float* __restrict__ t2W, const float* __restrict__ t2b,
    const float* __restrict__ v1W, const float* __restrict__ v1b,
    const float* __restrict__ v2W, const float* __restrict__ v2b,
    const float* __restrict__ v3W, const float* __restrict__ v3b,
    float* __restrict__ out)
{
    __shared__ float s_buf[6336];    // planes 0-1 -> h1/h [48][132] -> h_outT [64][50]
    __shared__ float s_asum[2304];   // AsumT[j][i] stride 48; overlaid by tail buffers
    __shared__ float s_h2[3072];     // plane 2 -> h2 [48][64]
    __shared__ float s_rinv[144];    // 3 planes x 48 rows
    __shared__ int   s_node[56];

    // overlays on s_asum (AsumT dead after GEMM3)
    float* s_gp   = s_asum;          // 1024 gate partials (8 x 128)
    float* s_g    = s_asum + 1024;   // 128
    float* s_t1   = s_asum + 1152;   // 128
    float* s_hf   = s_asum + 1280;   // 64
    float* s_hid  = s_asum + 1344;   // 160
    float* s_o1   = s_asum + 1504;   // 56
    float* s_o2   = s_asum + 1560;   // 56
    float* s_oe   = s_asum + 1616;   // 4
    float* s_ot   = s_asum + 1620;   // 4
    float* s_v2   = s_asum + 1624;   // 16

    const int b    = blockIdx.x;
    const int tid  = threadIdx.x;
    const int w    = tid >> 5;
    const int lane = tid & 31;

    if (tid < 56) s_node[tid] = Nmat[b * 56 + tid];

    // ---- Phase 1: AsumT[j][i] = sum_r adj[r][i][j] / (rowsum[r][i]+1) ----
    // All 3 planes staged at once: planes 0,1 in s_buf[0..4607], plane 2 in s_h2[0..2303].
    {
        const float4* a4 = (const float4*)(adj + (size_t)b * 6912);  // 1728 float4
        float4* p01 = (float4*)s_buf;
        float4* p2  = (float4*)s_h2;
        #pragma unroll
        for (int t = 0; t < 7; t++) {
            int i = tid + t * NTHREADS;
            if (i < 1728) {
                float4 v = a4[i];
                if (i < 1152) p01[i] = v; else p2[i - 1152] = v;
            }
        }
        __syncthreads();
        if (tid < 144) {
            int p = tid / 48, row = tid - p * 48;
            const float* base = (p == 0) ? s_buf : (p == 1) ? (s_buf + 2304) : s_h2;
            const float4* rp = (const float4*)&base[row * 48];
            float s = 0.f;
            #pragma unroll
            for (int t = 0; t < 12; t++) {
                float4 v = rp[t];
                s += (v.x + v.y) + (v.z + v.w);
            }
            s_rinv[tid] = __fdividef(1.f, s + 1.f);
        }
        __syncthreads();
        #pragma unroll
        for (int t = 0; t < 9; t++) {
            int idx = tid + t * NTHREADS;      // 0..2303
            int i = idx / 48, j = idx - i * 48;
            float v = s_buf[idx]        * s_rinv[i]
                    + s_buf[2304 + idx] * s_rinv[48 + i]
                    + s_h2[idx]         * s_rinv[96 + i];
            s_asum[j * 48 + i] = v;            // transposed store (s_asum disjoint)
        }
    }
    __syncthreads();

    // ---- h1 = W1[node[j]] + b1  -> s_buf as [48][HSTRIDE] ----
    for (int t = tid; t < 1536; t += NTHREADS) {
        int j = t >> 5, d4 = (t & 31) << 2;
        float4 ww = *(const float4*)&W1[s_node[j] * 128 + d4];
        float4 bb = *(const float4*)&b1[d4];
        *(float4*)&s_buf[j * HSTRIDE + d4] =
            make_float4(ww.x + bb.x, ww.y + bb.y, ww.z + bb.z, ww.w + bb.w);
    }
    __syncthreads();

    // ---- GEMM1: h = tanh(Asum @ h1 + h1), in place in s_buf ----
    // 8 warps: warp tile 12i x 64d (4x2), thread tile 3i x 8d
    {
        const int wi = w >> 1, wd = w & 1;
        const int li = lane & 3, ld = lane >> 2;
        const int i0 = wi * 12 + li * 3;
        const int d0 = wd * 64 + ld * 8;
        u64 acc[3][4];
        #pragma unroll
        for (int r = 0; r < 3; r++)
            #pragma unroll
            for (int p = 0; p < 4; p++) acc[r][p] = 0ull;
        #pragma unroll 2
        for (int j = 0; j < 48; j++) {
            const float* ap = &s_asum[j * 48 + i0];
            float a0 = ap[0], a1 = ap[1], a2 = ap[2];
            ulonglong2 hA = *(const ulonglong2*)&s_buf[j * HSTRIDE + d0];
            ulonglong2 hB = *(const ulonglong2*)&s_buf[j * HSTRIDE + d0 + 4];
            float av[3] = {a0, a1, a2};
            #pragma unroll
            for (int r = 0; r < 3; r++) {
                u64 aa = bc2(av[r]);
                acc[r][0] = f2fma(aa, hA.x, acc[r][0]);
                acc[r][1] = f2fma(aa, hA.y, acc[r][1]);
                acc[r][2] = f2fma(aa, hB.x, acc[r][2]);
                acc[r][3] = f2fma(aa, hB.y, acc[r][3]);
            }
        }
        float res[3][8];
        #pragma unroll
        for (int r = 0; r < 3; r++) {
            const float* row = &s_buf[(i0 + r) * HSTRIDE + d0];
            float4 r0 = *(const float4*)row;
            float4 r1 = *(const float4*)(row + 4);
            res[r][0] = r0.x; res[r][1] = r0.y; res[r][2] = r0.z; res[r][3] = r0.w;
            res[r][4] = r1.x; res[r][5] = r1.y; res[r][6] = r1.z; res[r][7] = r1.w;
        }
        __syncthreads();
        #pragma unroll
        for (int r = 0; r < 3; r++) {
            float2 a0 = up2(acc[r][0]), a1 = up2(acc[r][1]);
            float2 a2 = up2(acc[r][2]), a3 = up2(acc[r][3]);
            float* row = &s_buf[(i0 + r) * HSTRIDE + d0];
            *(float4*)row = make_float4(ftanh(a0.x + res[r][0]), ftanh(a0.y + res[r][1]),
                                        ftanh(a1.x + res[r][2]), ftanh(a1.y + res[r][3]));
            *(float4*)(row + 4) = make_float4(ftanh(a2.x + res[r][4]), ftanh(a2.y + res[r][5]),
                                              ftanh(a3.x + res[r][6]), ftanh(a3.y + res[r][7]));
        }
    }
    __syncthreads();

    // ---- GEMM2: h2 = h @ W2 + b2 -> s_h2 [48][64] ----
    // 8 warps: warp tile 12i x 32d (4x2), thread tile 3i x 4d
    {
        const int wi = w >> 1, wd = w & 1;
        const int li = lane & 3, ld = lane >> 2;
        const int i0 = wi * 12 + li * 3;
        const int d0 = wd * 32 + ld * 4;
        float4 bv = *(const float4*)&b2[d0];
        u64 acc[3][2];
        #pragma unroll
        for (int r = 0; r < 3; r++) { acc[r][0] = pk2(bv.x, bv.y); acc[r][1] = pk2(bv.z, bv.w); }
        #pragma unroll 2
        for (int k4 = 0; k4 < 32; k4++) {
            float hr[3][4];
            #pragma unroll
            for (int r = 0; r < 3; r++) {
                float4 hv = *(const float4*)&s_buf[(i0 + r) * HSTRIDE + k4 * 4];
                hr[r][0] = hv.x; hr[r][1] = hv.y; hr[r][2] = hv.z; hr[r][3] = hv.w;
            }
            #pragma unroll
            for (int kk = 0; kk < 4; kk++) {
                ulonglong2 wrow = *(const ulonglong2*)&W2[(k4 * 4 + kk) * 64 + d0];
                #pragma unroll
                for (int r = 0; r < 3; r++) {
                    u64 hb = bc2(hr[r][kk]);
                    acc[r][0] = f2fma(hb, wrow.x, acc[r][0]);
                    acc[r][1] = f2fma(hb, wrow.y, acc[r][1]);
                }
            }
        }
        #pragma unroll
        for (int r = 0; r < 3; r++) {
            float2 a0 = up2(acc[r][0]), a1 = up2(acc[r][1]);
            *(float4*)&s_h2[(i0 + r) * 64 + d0] = make_float4(a0.x, a0.y, a1.x, a1.y);
        }
    }
    __syncthreads();

    // ---- GEMM3: h_outT[d][i] = tanh(Asum @ h2 + h2) -> s_buf [64][TSTRIDE] ----
    // 8 warps: warp tile 12i x 32d (4x2), thread tile 3i x 4d
    {
        const int wi = w >> 1, wd = w & 1;
        const int li = lane & 3, ld = lane >> 2;
        const int i0 = wi * 12 + li * 3;
        const int d0 = wd * 32 + ld * 4;
        u64 acc[3][2];
        #pragma unroll
        for (int r = 0; r < 3; r++) { acc[r][0] = 0ull; acc[r][1] = 0ull; }
        #pragma unroll 2
        for (int j = 0; j < 48; j++) {
            const float* ap = &s_asum[j * 48 + i0];
            float a0 = ap[0], a1 = ap[1], a2 = ap[2];
            ulonglong2 hv = *(const ulonglong2*)&s_h2[j * 64 + d0];
            float av[3] = {a0, a1, a2};
            #pragma unroll
            for (int r = 0; r < 3; r++) {
                u64 aa = bc2(av[r]);
                acc[r][0] = f2fma(aa, hv.x, acc[r][0]);
                acc[r][1] = f2fma(aa, hv.y, acc[r][1]);
            }
        }
        float t[3][4];
        #pragma unroll
        for (int r = 0; r < 3; r++) {
            float4 res = *(const float4*)&s_h2[(i0 + r) * 64 + d0];
            float2 a0 = up2(acc[r][0]), a1 = up2(acc[r][1]);
            t[r][0] = ftanh(a0.x + res.x);
            t[r][1] = ftanh(a0.y + res.y);
            t[r][2] = ftanh(a1.x + res.z);
            t[r][3] = ftanh(a1.y + res.w);
        }
        // transposed store, stride TSTRIDE (scalar; benign 2-way bank overlap)
        #pragma unroll
        for (int c = 0; c < 4; c++) {
            float* col = &s_buf[(d0 + c) * TSTRIDE + i0];
            col[0] = t[0][c];
            col[1] = t[1][c];
            col[2] = t[2][c];
        }
    }
    __syncthreads();

    // ---- Gate: S/T GEMMs (48x128, K=64) + fused sigmoid/tanh + node reduction ----
    // 8 warps: warp tile 24i x 32d, thread tile 6i x 4d (both S and T)
    {
        const int wi = w >> 2, wd = w & 3;
        const int li = lane >> 3, ld = lane & 7;
        const int i0 = wi * 24 + li * 6;
        const int d0 = wd * 32 + ld * 4;
        u64 aS[6][2], aT6[6][2];
        #pragma unroll
        for (int ii = 0; ii < 6; ii++) {
            aS[ii][0] = 0ull; aS[ii][1] = 0ull;
            aT6[ii][0] = 0ull; aT6[ii][1] = 0ull;
        }
        for (int k = 0; k < 64; k++) {
            const float* hrow = &s_buf[k * TSTRIDE + i0];
            float2 h01 = *(const float2*)hrow;
            float2 h23 = *(const float2*)(hrow + 2);
            float2 h45 = *(const float2*)(hrow + 4);
            ulonglong2 ws = *(const ulonglong2*)&asW[k * 128 + d0];
            ulonglong2 wt = *(const ulonglong2*)&atW[k * 128 + d0];
            float hv[6] = {h01.x, h01.y, h23.x, h23.y, h45.x, h45.y};
            #pragma unroll
            for (int ii = 0; ii < 6; ii++) {
                u64 hb = bc2(hv[ii]);
                aS[ii][0]  = f2fma(hb, ws.x, aS[ii][0]);
                aS[ii][1]  = f2fma(hb, ws.y, aS[ii][1]);
                aT6[ii][0] = f2fma(hb, wt.x, aT6[ii][0]);
                aT6[ii][1] = f2fma(hb, wt.y, aT6[ii][1]);
            }
        }
        float4 sbv = *(const float4*)&asb[d0];
        float4 tbv = *(const float4*)&atb[d0];
        float sum0 = 0.f, sum1 = 0.f, sum2 = 0.f, sum3 = 0.f;
        #pragma unroll
        for (int ii = 0; ii < 6; ii++) {
            int nd = s_node[i0 + ii];
            float4 wso = *(const float4*)&asW[(64 + nd) * 128 + d0];
            float4 wto = *(const float4*)&atW[(64 + nd) * 128 + d0];
            float2 s01 = up2(aS[ii][0]), s23 = up2(aS[ii][1]);
            float2 t01 = up2(aT6[ii][0]), t23 = up2(aT6[ii][1]);
            sum0 += fsig(s01.x + wso.x + sbv.x) * ftanh(t01.x + wto.x + tbv.x);
            sum1 += fsig(s01.y + wso.y + sbv.y) * ftanh(t01.y + wto.y + tbv.y);
            sum2 += fsig(s23.x + wso.z + sbv.z) * ftanh(t23.x + wto.z + tbv.z);
            sum3 += fsig(s23.y + wso.w + sbv.w) * ftanh(t23.y + wto.w + tbv.w);
        }
        *(float4*)&s_gp[(wi * 4 + li) * 128 + d0] = make_float4(sum0, sum1, sum2, sum3);
    }
    __syncthreads();
    if (tid < 128) {
        float s = 0.f;
        #pragma unroll
        for (int r = 0; r < 8; r++) s += s_gp[r * 128 + tid];
        s_g[tid] = ftanh(s);
    }
    __syncthreads();

    // ---- hfeat = (g @ l1W + l1b) @ l2W + l2b ----
    // l1: lane-pair k-split (half = tid&1), shuffle combine -> s_t1 (no partial array)
    {
        int c = tid >> 1, half = tid & 1;
        int k0 = half * 64;
        float acc = 0.f;
        #pragma unroll 4
        for (int k = 0; k < 64; k++) acc += s_g[k0 + k] * l1W[(k0 + k) * 128 + c];
        acc += __shfl_xor_sync(0xffffffffu, acc, 1);
        if (half == 0) s_t1[c] = l1b[c] + acc;
    }
    __syncthreads();
    // l2: lane-quad k-split (q = tid&3), shuffle combine -> s_hf
    {
        int c = tid >> 2, q = tid & 3;
        int k0 = q * 32;
        float acc = 0.f;
        #pragma unroll 4
        for (int k = 0; k < 32; k++) acc += s_t1[k0 + k] * l2W[(k0 + k) * 64 + c];
        acc += __shfl_xor_sync(0xffffffffu, acc, 1);
        acc += __shfl_xor_sync(0xffffffffu, acc, 2);
        if (q == 0) s_hf[c] = l2b[c] + acc;
    }
    __syncthreads();

    // ---- Heads stage A: five 64->32 matvecs with leaky-relu ----
    if (tid < 160) {
        const int head = tid >> 5, u = tid & 31;
        const float* Wm;
        float acc;
        if      (head == 0) { Wm = f1;  acc = 0.f; }
        else if (head == 1) { Wm = s1;  acc = 0.f; }
        else if (head == 2) { Wm = e1;  acc = 0.f; }
        else if (head == 3) { Wm = t1W; acc = t1b[u]; }
        else                { Wm = v1W; acc = v1b[u]; }
        #pragma unroll 4
        for (int k = 0; k < 64; k++) acc += s_hf[k] * Wm[k * 32 + u];
        s_hid[tid] = lrelu(acc);
    }
    __syncthreads();

    // ---- Heads stage B ----
    if (tid < 56) {
        float acc = 0.f;
        #pragma unroll
        for (int u = 0; u < 32; u++) acc += s_hid[u] * f2[u * 56 + tid];
        bool ex = (s_node[tid] > 0) && (tid < 48);
        s_o1[tid] = acc + (ex ? 0.f : -10000.f);
    } else if (tid < 112) {
        int j = tid - 56;
        float acc = 0.f;
        #pragma unroll
        for (int u = 0; u < 32; u++) acc += s_hid[32 + u] * s2[u * 56 + j];
        s_o2[j] = acc;
    } else if (tid < 115) {
        int j = tid - 112;
        float acc = 0.f;
        #pragma unroll
        for (int u = 0; u < 32; u++) acc += s_hid[64 + u] * e2[u * 3 + j];
        s_oe[j] = acc;
    } else if (tid < 117) {
        int j = tid - 115;
        float acc = t2b[j];
        #pragma unroll
        for (int u = 0; u < 32; u++) acc += s_hid[96 + u] * t2W[u * 2 + j];
        s_ot[j] = acc;
    } else if (tid < 133) {
        int m = tid - 117;
        float acc = v2b[m];
        #pragma unroll
        for (int u = 0; u < 32; u++) acc += s_hid[128 + u] * v2W[u * 16 + m];
        s_v2[m] = lrelu(acc);
    }
    __syncthreads();

    // ---- Tail: warp-parallel softmaxes / argmax / value (single sync above) ----
    float* ob = out + (size_t)b * 118;
    if (w == 0) {
        // --- p1 = softmax(masked o1); first = argmax (first-max tie-break) ---
        float vlo = s_o1[lane];                               // idx = lane (0..31)
        float vhi = (lane < 24) ? s_o1[lane + 32] : -3.4e38f; // idx = lane+32 (32..55)
        float bv = vlo; int bi = lane;
        if (vhi > bv) { bv = vhi; bi = lane + 32; }           // prefer lower idx on tie
        #pragma unroll
        for (int off = 16; off; off >>= 1) {
            float ov = __shfl_xor_sync(0xffffffffu, bv, off);
            int   oi = __shfl_xor_sync(0xffffffffu, bi, off);
            if (ov > bv || (ov == bv && oi < bi)) { bv = ov; bi = oi; }
        }
        float e0 = __expf(vlo - bv);
        float e1 = (lane < 24) ? __expf(vhi - bv) : 0.f;
        float ssum = e0 + e1;
        #pragma unroll
        for (int off = 16; off; off >>= 1) ssum += __shfl_xor_sync(0xffffffffu, ssum, off);
        float inv = __fdividef(1.f, ssum);
        ob[lane] = e0 * inv;
        if (lane < 24) ob[lane + 32] = e1 * inv;

        // --- p2 = softmax(masked o2), mask uses `first` (in-warp, no sync) ---
        const int first = bi;
        bool exlo = (((s_node[lane] > 0) && (lane < 48))) && (lane != first);
        float u0 = s_o2[lane] + (exlo ? 0.f : -10000.f);
        float u1 = -3.4e38f;
        if (lane < 24) {
            int j = lane + 32;
            bool exhi = (((s_node[j] > 0) && (j < 48)) || (j >= 48)) && (j != first);
            u1 = s_o2[j] + (exhi ? 0.f : -10000.f);
        }
        float mx = fmaxf(u0, u1);
        #pragma unroll
        for (int off = 16; off; off >>= 1) mx = fmaxf(mx, __shfl_xor_sync(0xffffffffu, mx, off));
        float f0 = __expf(u0 - mx);
        float f1 = (lane < 24) ? __expf(u1 - mx) : 0.f;
        float s2s = f0 + f1;
        #pragma unroll
        for (int off = 16; off; off >>= 1) s2s += __shfl_xor_sync(0xffffffffu, s2s, off);
        float inv2 = __fdividef(1.f, s2s);
        ob[56 + lane] = f0 * inv2;
        if (lane < 24) ob[56 + lane + 32] = f1 * inv2;
    } else if (w == 1) {
        if (lane == 0) {
            float me = fmaxf(s_oe[0], fmaxf(s_oe[1], s_oe[2]));
            float e0 = __expf(s_oe[0] - me), e1v = __expf(s_oe[1] - me), e2v = __expf(s_oe[2] - me);
            float inv = __fdividef(1.f, e0 + e1v + e2v);
            ob[112] = e0 * inv; ob[113] = e1v * inv; ob[114] = e2v * inv;
        } else if (lane == 1) {
            float mt = fmaxf(s_ot[0], s_ot[1]);
            float p0 = __expf(s_ot[0] - mt), p1 = __expf(s_ot[1] - mt);
            float invt = __fdividef(1.f, p0 + p1);
            ob[115] = p0 * invt; ob[116] = p1 * invt;
        } else if (lane == 2) {
            float acc = v3b[0];
            #pragma unroll
            for (int m = 0; m < 16; m++) acc += s_v2[m] * v3W[m];
            ob[117] = acc;
        }
    }
}

extern "C" void kernel_launch(void* const* d_in, const int* in_sizes, int n_in,
                              void* d_out, int out_size) {
    (void)in_sizes; (void)n_in; (void)out_size;
    policy_kernel<<<8192, NTHREADS>>>(
        (const int*)  d_in[0],  (const float*)d_in[1],
        (const float*)d_in[2],  (const float*)d_in[3],
        (const float*)d_in[4],  (const float*)d_in[5],
        (const float*)d_in[6],  (const float*)d_in[7],
        (const float*)d_in[8],  (const float*)d_in[9],
        (const float*)d_in[10], (const float*)d_in[11],
        (const float*)d_in[12], (const float*)d_in[13],
        (const float*)d_in[14], (const float*)d_in[15],
        (const float*)d_in[16], (const float*)d_in[17],
        (const float*)d_in[18], (const float*)d_in[19],
        (const float*)d_in[20], (const float*)d_in[21],
        (const float*)d_in[22], (const float*)d_in[23],
        (const float*)d_in[24], (const float*)d_in[25],
        (const float*)d_in[26], (const float*)d_in[27],
        (const float*)d_in[28], (const float*)d_in[29],
        (float*)d_out);
}

// round 17
// speedup vs baseline: 1.0954x; 1.0954x over previous
#include <cuda_runtime.h>
#include <math.h>

#define NTHREADS 256
#define HSTRIDE 132   // padded stride for h1/h [48][132] (bank-conflict fix)
#define TSTRIDE 50    // padded stride for h_outT [64][50]

typedef unsigned long long u64;

__device__ __forceinline__ u64 pk2(float x, float y) {
    u64 r; asm("mov.b64 %0, {%1,%2};" : "=l"(r) : "f"(x), "f"(y)); return r;
}
__device__ __forceinline__ u64 bc2(float x) { return pk2(x, x); }
__device__ __forceinline__ u64 f2fma(u64 a, u64 b, u64 c) {
    u64 d; asm("fma.rn.f32x2 %0, %1, %2, %3;" : "=l"(d) : "l"(a), "l"(b), "l"(c)); return d;
}
__device__ __forceinline__ float2 up2(u64 v) {
    float lo, hi; asm("mov.b64 {%0,%1}, %2;" : "=f"(lo), "=f"(hi) : "l"(v));
    return make_float2(lo, hi);
}

__device__ __forceinline__ float lrelu(float x) { return x > 0.f ? x : 0.1f * x; }
__device__ __forceinline__ float fsig(float x) {
    return __fdividef(1.f, 1.f + __expf(-x));
}
__device__ __forceinline__ float ftanh(float x) {
    return 1.f - __fdividef(2.f, __expf(2.f * x) + 1.f);
}

__global__ __launch_bounds__(NTHREADS, 3) void policy_kernel(
    const int*   __restrict__ Nmat,   // [B,56] int32
    const float* __restrict__ adj,    // [B,3,48,48]
    const float* __restrict__ W1,  const float* __restrict__ b1,
    const float* __restrict__ W2,  const float* __restrict__ b2,
    const float* __restrict__ asW, const float* __restrict__ asb,
    const float* __restrict__ atW, const float* __restrict__ atb,
    const float* __restrict__ l1W, const float* __restrict__ l1b,
    const float* __restrict__ l2W, const float* __restrict__ l2b,
    const float* __restrict__ f1,  const float* __restrict__ f2,
    const float* __restrict__ s1,  const float* __restrict__ s2,
    const float* __restrict__ e1,  const float* __restrict__ e2,
    const float* __restrict__ t1W, const float* __restrict__ t1b,
    const float* __restrict__ t2W, const float* __restrict__ t2b,
    const float* __restrict__ v1W, const float* __restrict__ v1b,
    const float* __restrict__ v2W, const float* __restrict__ v2b,
    const float* __restrict__ v3W, const float* __restrict__ v3b,
    float* __restrict__ out)
{
    __shared__ float s_buf[6336];    // planes 0-1 -> h1/h [48][132] -> h_outT [64][50]
    __shared__ float s_asum[2304];   // AsumT[j][i] stride 48; overlaid by tail buffers
    __shared__ float s_h2[3072];     // plane 2 -> h2 [48][64]
    __shared__ float s_rinv[144];    // 3 planes x 48 rows
    __shared__ int   s_node[56];

    // overlays on s_asum (AsumT dead after GEMM3)
    float* s_gp   = s_asum;          // 1024 gate partials (8 x 128)
    float* s_g    = s_asum + 1024;   // 128
    float* s_t1   = s_asum + 1152;   // 128
    float* s_hf   = s_asum + 1280;   // 64
    float* s_hid  = s_asum + 1344;   // 160
    float* s_o1   = s_asum + 1504;   // 56
    float* s_o2   = s_asum + 1560;   // 56
    float* s_oe   = s_asum + 1616;   // 4
    float* s_ot   = s_asum + 1620;   // 4
    float* s_v2   = s_asum + 1624;   // 16

    const int b    = blockIdx.x;
    const int tid  = threadIdx.x;
    const int w    = tid >> 5;
    const int lane = tid & 31;

    if (tid < 56) s_node[tid] = Nmat[b * 56 + tid];

    // ---- Phase 1: AsumT[j][i] = sum_r adj[r][i][j] / (rowsum[r][i]+1) ----
    // All 3 planes staged at once: planes 0,1 in s_buf[0..4607], plane 2 in s_h2[0..2303].
    {
        const float4* a4 = (const float4*)(adj + (size_t)b * 6912);  // 1728 float4
        float4* p01 = (float4*)s_buf;
        float4* p2  = (float4*)s_h2;
        #pragma unroll
        for (int t = 0; t < 7; t++) {
            int i = tid + t * NTHREADS;
            if (i < 1728) {
                float4 v = a4[i];
                if (i < 1152) p01[i] = v; else p2[i - 1152] = v;
            }
        }
        __syncthreads();
        if (tid < 144) {
            int p = tid / 48, row = tid - p * 48;
            const float* base = (p == 0) ? s_buf : (p == 1) ? (s_buf + 2304) : s_h2;
            const float4* rp = (const float4*)&base[row * 48];
            float s = 0.f;
            #pragma unroll
            for (int t = 0; t < 12; t++) {
                float4 v = rp[t];
                s += (v.x + v.y) + (v.z + v.w);
            }
            s_rinv[tid] = __fdividef(1.f, s + 1.f);
        }
        __syncthreads();
        #pragma unroll
        for (int t = 0; t < 9; t++) {
            int idx = tid + t * NTHREADS;      // 0..2303
            int i = idx / 48, j = idx - i * 48;
            float v = s_buf[idx]        * s_rinv[i]
                    + s_buf[2304 + idx] * s_rinv[48 + i]
                    + s_h2[idx]         * s_rinv[96 + i];
            s_asum[j * 48 + i] = v;            // transposed store (s_asum disjoint)
        }
    }
    __syncthreads();

    // ---- h1 = W1[node[j]] + b1  -> s_buf as [48][HSTRIDE] ----
    for (int t = tid; t < 1536; t += NTHREADS) {
        int j = t >> 5, d4 = (t & 31) << 2;
        float4 ww = *(const float4*)&W1[s_node[j] * 128 + d4];
        float4 bb = *(const float4*)&b1[d4];
        *(float4*)&s_buf[j * HSTRIDE + d4] =
            make_float4(ww.x + bb.x, ww.y + bb.y, ww.z + bb.z, ww.w + bb.w);
    }
    __syncthreads();

    // ---- GEMM1: h = tanh(Asum @ h1 + h1), in place in s_buf ----
    // 8 warps: warp tile 12i x 64d (4x2), thread tile 3i x 8d
    {
        const int wi = w >> 1, wd = w & 1;
        const int li = lane & 3, ld = lane >> 2;
        const int i0 = wi * 12 + li * 3;
        const int d0 = wd * 64 + ld * 8;
        u64 acc[3][4];
        #pragma unroll
        for (int r = 0; r < 3; r++)
            #pragma unroll
            for (int p = 0; p < 4; p++) acc[r][p] = 0ull;
        #pragma unroll 2
        for (int j = 0; j < 48; j++) {
            const float* ap = &s_asum[j * 48 + i0];
            float a0 = ap[0], a1 = ap[1], a2 = ap[2];
            ulonglong2 hA = *(const ulonglong2*)&s_buf[j * HSTRIDE + d0];
            ulonglong2 hB = *(const ulonglong2*)&s_buf[j * HSTRIDE + d0 + 4];
            float av[3] = {a0, a1, a2};
            #pragma unroll
            for (int r = 0; r < 3; r++) {
                u64 aa = bc2(av[r]);
                acc[r][0] = f2fma(aa, hA.x, acc[r][0]);
                acc[r][1] = f2fma(aa, hA.y, acc[r][1]);
                acc[r][2] = f2fma(aa, hB.x, acc[r][2]);
                acc[r][3] = f2fma(aa, hB.y, acc[r][3]);
            }
        }
        float res[3][8];
        #pragma unroll
        for (int r = 0; r < 3; r++) {
            const float* row = &s_buf[(i0 + r) * HSTRIDE + d0];
            float4 r0 = *(const float4*)row;
            float4 r1 = *(const float4*)(row + 4);
            res[r][0] = r0.x; res[r][1] = r0.y; res[r][2] = r0.z; res[r][3] = r0.w;
            res[r][4] = r1.x; res[r][5] = r1.y; res[r][6] = r1.z; res[r][7] = r1.w;
        }
        __syncthreads();
        #pragma unroll
        for (int r = 0; r < 3; r++) {
            float2 a0 = up2(acc[r][0]), a1 = up2(acc[r][1]);
            float2 a2 = up2(acc[r][2]), a3 = up2(acc[r][3]);
            float* row = &s_buf[(i0 + r) * HSTRIDE + d0];
            *(float4*)row = make_float4(ftanh(a0.x + res[r][0]), ftanh(a0.y + res[r][1]),
                                        ftanh(a1.x + res[r][2]), ftanh(a1.y + res[r][3]));
            *(float4*)(row + 4) = make_float4(ftanh(a2.x + res[r][4]), ftanh(a2.y + res[r][5]),
                                              ftanh(a3.x + res[r][6]), ftanh(a3.y + res[r][7]));
        }
    }
    __syncthreads();

    // ---- GEMM2: h2 = h @ W2 + b2 -> s_h2 [48][64] ----
    // 8 warps: warp tile 12i x 32d (4x2), thread tile 3i x 4d
    {
        const int wi = w >> 1, wd = w & 1;
        const int li = lane & 3, ld = lane >> 2;
        const int i0 = wi * 12 + li * 3;
        const int d0 = wd * 32 + ld * 4;
        float4 bv = *(const float4*)&b2[d0];
        u64 acc[3][2];
        #pragma unroll
        for (int r = 0; r < 3; r++) { acc[r][0] = pk2(bv.x, bv.y); acc[r][1] = pk2(bv.z, bv.w); }
        #pragma unroll 2
        for (int k4 = 0; k4 < 32; k4++) {
            float hr[3][4];
            #pragma unroll
            for (int r = 0; r < 3; r++) {
                float4 hv = *(const float4*)&s_buf[(i0 + r) * HSTRIDE + k4 * 4];
                hr[r][0] = hv.x; hr[r][1] = hv.y; hr[r][2] = hv.z; hr[r][3] = hv.w;
            }
            #pragma unroll
            for (int kk = 0; kk < 4; kk++) {
                ulonglong2 wrow = *(const ulonglong2*)&W2[(k4 * 4 + kk) * 64 + d0];
                #pragma unroll
                for (int r = 0; r < 3; r++) {
                    u64 hb = bc2(hr[r][kk]);
                    acc[r][0] = f2fma(hb, wrow.x, acc[r][0]);
                    acc[r][1] = f2fma(hb, wrow.y, acc[r][1]);
                }
            }
        }
        #pragma unroll
        for (int r = 0; r < 3; r++) {
            float2 a0 = up2(acc[r][0]), a1 = up2(acc[r][1]);
            *(float4*)&s_h2[(i0 + r) * 64 + d0] = make_float4(a0.x, a0.y, a1.x, a1.y);
        }
    }
    __syncthreads();

    // ---- GEMM3: h_outT[d][i] = tanh(Asum @ h2 + h2) -> s_buf [64][TSTRIDE] ----
    // 8 warps: warp tile 12i x 32d (4x2), thread tile 3i x 4d
    {
        const int wi = w >> 1, wd = w & 1;
        const int li = lane & 3, ld = lane >> 2;
        const int i0 = wi * 12 + li * 3;
        const int d0 = wd * 32 + ld * 4;
        u64 acc[3][2];
        #pragma unroll
        for (int r = 0; r < 3; r++) { acc[r][0] = 0ull; acc[r][1] = 0ull; }
        #pragma unroll 2
        for (int j = 0; j < 48; j++) {
            const float* ap = &s_asum[j * 48 + i0];
            float a0 = ap[0], a1 = ap[1], a2 = ap[2];
            ulonglong2 hv = *(const ulonglong2*)&s_h2[j * 64 + d0];
            float av[3] = {a0, a1, a2};
            #pragma unroll
            for (int r = 0; r < 3; r++) {
                u64 aa = bc2(av[r]);
                acc[r][0] = f2fma(aa, hv.x, acc[r][0]);
                acc[r][1] = f2fma(aa, hv.y, acc[r][1]);
            }
        }
        float t[3][4];
        #pragma unroll
        for (int r = 0; r < 3; r++) {
            float4 res = *(const float4*)&s_h2[(i0 + r) * 64 + d0];
            float2 a0 = up2(acc[r][0]), a1 = up2(acc[r][1]);
            t[r][0] = ftanh(a0.x + res.x);
            t[r][1] = ftanh(a0.y + res.y);
            t[r][2] = ftanh(a1.x + res.z);
            t[r][3] = ftanh(a1.y + res.w);
        }
        // transposed store, stride TSTRIDE (scalar; benign 2-way bank overlap)
        #pragma unroll
        for (int c = 0; c < 4; c++) {
            float* col = &s_buf[(d0 + c) * TSTRIDE + i0];
            col[0] = t[0][c];
            col[1] = t[1][c];
            col[2] = t[2][c];
        }
    }
    __syncthreads();

    // ---- Gate: S/T GEMMs (48x128, K=64) + fused sigmoid/tanh + node reduction ----
    // 8 warps: warp tile 24i x 32d, thread tile 6i x 4d (both S and T)
    {
        const int wi = w >> 2, wd = w & 3;
        const int li = lane >> 3, ld = lane & 7;
        const int i0 = wi * 24 + li * 6;
        const int d0 = wd * 32 + ld * 4;
        u64 aS[6][2], aT6[6][2];
        #pragma unroll
        for (int ii = 0; ii < 6; ii++) {
            aS[ii][0] = 0ull; aS[ii][1] = 0ull;
            aT6[ii][0] = 0ull; aT6[ii][1] = 0ull;
        }
        for (int k = 0; k < 64; k++) {
            const float* hrow = &s_buf[k * TSTRIDE + i0];
            float2 h01 = *(const float2*)hrow;
            float2 h23 = *(const float2*)(hrow + 2);
            float2 h45 = *(const float2*)(hrow + 4);
            ulonglong2 ws = *(const ulonglong2*)&asW[k * 128 + d0];
            ulonglong2 wt = *(const ulonglong2*)&atW[k * 128 + d0];
            float hv[6] = {h01.x, h01.y, h23.x, h23.y, h45.x, h45.y};
            #pragma unroll
            for (int ii = 0; ii < 6; ii++) {
                u64 hb = bc2(hv[ii]);
                aS[ii][0]  = f2fma(hb, ws.x, aS[ii][0]);
                aS[ii][1]  = f2fma(hb, ws.y, aS[ii][1]);
                aT6[ii][0] = f2fma(hb, wt.x, aT6[ii][0]);
                aT6[ii][1] = f2fma(hb, wt.y, aT6[ii][1]);
            }
        }
        float4 sbv = *(const float4*)&asb[d0];
        float4 tbv = *(const float4*)&atb[d0];
        float sum0 = 0.f, sum1 = 0.f, sum2 = 0.f, sum3 = 0.f;
        #pragma unroll
        for (int ii = 0; ii < 6; ii++) {
            int nd = s_node[i0 + ii];
            float4 wso = *(const float4*)&asW[(64 + nd) * 128 + d0];
            float4 wto = *(const float4*)&atW[(64 + nd) * 128 + d0];
            float2 s01 = up2(aS[ii][0]), s23 = up2(aS[ii][1]);
            float2 t01 = up2(aT6[ii][0]), t23 = up2(aT6[ii][1]);
            sum0 += fsig(s01.x + wso.x + sbv.x) * ftanh(t01.x + wto.x + tbv.x);
            sum1 += fsig(s01.y + wso.y + sbv.y) * ftanh(t01.y + wto.y + tbv.y);
            sum2 += fsig(s23.x + wso.z + sbv.z) * ftanh(t23.x + wto.z + tbv.z);
            sum3 += fsig(s23.y + wso.w + sbv.w) * ftanh(t23.y + wto.w + tbv.w);
        }
        *(float4*)&s_gp[(wi * 4 + li) * 128 + d0] = make_float4(sum0, sum1, sum2, sum3);
    }
    __syncthreads();
    if (tid < 128) {
        float s = 0.f;
        #pragma unroll
        for (int r = 0; r < 8; r++) s += s_gp[r * 128 + tid];
        s_g[tid] = ftanh(s);
    }
    __syncthreads();

    // ---- hfeat = (g @ l1W + l1b) @ l2W + l2b  (k-split matvecs, dual accums) ----
    {
        int c = tid & 127, half = tid >> 7;
        int k0 = half * 64;
        const float* Wp = &l1W[k0 * 128 + c];
        float a0 = 0.f, a1 = 0.f;
        #pragma unroll 4
        for (int k = 0; k < 32; k++) {
            a0 += s_g[k0 + k]      * Wp[k * 128];
            a1 += s_g[k0 + 32 + k] * Wp[(32 + k) * 128];
        }
        s_gp[half * 128 + c] = a0 + a1;
    }
    __syncthreads();
    if (tid < 128) s_t1[tid] = l1b[tid] + s_gp[tid] + s_gp[128 + tid];
    __syncthreads();
    {
        int c = tid & 63, qq = tid >> 6;
        int k0 = qq * 32;
        const float* Wp = &l2W[k0 * 64 + c];
        float a0 = 0.f, a1 = 0.f;
        #pragma unroll 4
        for (int k = 0; k < 16; k++) {
            a0 += s_t1[k0 + k]      * Wp[k * 64];
            a1 += s_t1[k0 + 16 + k] * Wp[(16 + k) * 64];
        }
        s_gp[qq * 64 + c] = a0 + a1;
    }
    __syncthreads();
    if (tid < 64)
        s_hf[tid] = l2b[tid] + s_gp[tid] + s_gp[64 + tid] + s_gp[128 + tid] + s_gp[192 + tid];
    __syncthreads();

    // ---- Heads stage A: five 64->32 matvecs with leaky-relu (dual accums) ----
    if (tid < 160) {
        const int head = tid >> 5, u = tid & 31;
        const float* Wm;
        float bias;
        if      (head == 0) { Wm = f1;  bias = 0.f; }
        else if (head == 1) { Wm = s1;  bias = 0.f; }
        else if (head == 2) { Wm = e1;  bias = 0.f; }
        else if (head == 3) { Wm = t1W; bias = t1b[u]; }
        else                { Wm = v1W; bias = v1b[u]; }
        const float* Wp = Wm + u;
        float a0 = 0.f, a1 = 0.f;
        #pragma unroll 4
        for (int k = 0; k < 32; k++) {
            a0 += s_hf[k]      * Wp[k * 32];
            a1 += s_hf[32 + k] * Wp[(32 + k) * 32];
        }
        s_hid[tid] = lrelu(bias + a0 + a1);
    }
    __syncthreads();

    // ---- Heads stage B ----
    if (tid < 56) {
        float acc = 0.f;
        #pragma unroll
        for (int u = 0; u < 32; u++) acc += s_hid[u] * f2[u * 56 + tid];
        bool ex = (s_node[tid] > 0) && (tid < 48);
        s_o1[tid] = acc + (ex ? 0.f : -10000.f);
    } else if (tid < 112) {
        int j = tid - 56;
        float acc = 0.f;
        #pragma unroll
        for (int u = 0; u < 32; u++) acc += s_hid[32 + u] * s2[u * 56 + j];
        s_o2[j] = acc;
    } else if (tid < 115) {
        int j = tid - 112;
        float acc = 0.f;
        #pragma unroll
        for (int u = 0; u < 32; u++) acc += s_hid[64 + u] * e2[u * 3 + j];
        s_oe[j] = acc;
    } else if (tid < 117) {
        int j = tid - 115;
        float acc = t2b[j];
        #pragma unroll
        for (int u = 0; u < 32; u++) acc += s_hid[96 + u] * t2W[u * 2 + j];
        s_ot[j] = acc;
    } else if (tid < 133) {
        int m = tid - 117;
        float acc = v2b[m];
        #pragma unroll
        for (int u = 0; u < 32; u++) acc += s_hid[128 + u] * v2W[u * 16 + m];
        s_v2[m] = lrelu(acc);
    }
    __syncthreads();

    // ---- Tail: warp-parallel softmaxes / argmax / value (single sync above) ----
    float* ob = out + (size_t)b * 118;
    if (w == 0) {
        // --- p1 = softmax(masked o1); first = argmax (first-max tie-break) ---
        float vlo = s_o1[lane];                               // idx = lane (0..31)
        float vhi = (lane < 24) ? s_o1[lane + 32] : -3.4e38f; // idx = lane+32 (32..55)
        float bv = vlo; int bi = lane;
        if (vhi > bv) { bv = vhi; bi = lane + 32; }           // prefer lower idx on tie
        #pragma unroll
        for (int off = 16; off; off >>= 1) {
            float ov = __shfl_xor_sync(0xffffffffu, bv, off);
            int   oi = __shfl_xor_sync(0xffffffffu, bi, off);
            if (ov > bv || (ov == bv && oi < bi)) { bv = ov; bi = oi; }
        }
        float e0 = __expf(vlo - bv);
        float e1 = (lane < 24) ? __expf(vhi - bv) : 0.f;
        float ssum = e0 + e1;
        #pragma unroll
        for (int off = 16; off; off >>= 1) ssum += __shfl_xor_sync(0xffffffffu, ssum, off);
        float inv = __fdividef(1.f, ssum);
        ob[lane] = e0 * inv;
        if (lane < 24) ob[lane + 32] = e1 * inv;

        // --- p2 = softmax(masked o2), mask uses `first` (in-warp, no sync) ---
        const int first = bi;
        bool exlo = (((s_node[lane] > 0) && (lane < 48))) && (lane != first);
        float u0 = s_o2[lane] + (exlo ? 0.f : -10000.f);
        float u1 = -3.4e38f;
        if (lane < 24) {
            int j = lane + 32;
            bool exhi = (((s_node[j] > 0) && (j < 48)) || (j >= 48)) && (j != first);
            u1 = s_o2[j] + (exhi ? 0.f : -10000.f);
        }
        float mx = fmaxf(u0, u1);
        #pragma unroll
        for (int off = 16; off; off >>= 1) mx = fmaxf(mx, __shfl_xor_sync(0xffffffffu, mx, off));
        float f0 = __expf(u0 - mx);
        float f1 = (lane < 24) ? __expf(u1 - mx) : 0.f;
        float s2s = f0 + f1;
        #pragma unroll
        for (int off = 16; off; off >>= 1) s2s += __shfl_xor_sync(0xffffffffu, s2s, off);
        float inv2 = __fdividef(1.f, s2s);
        ob[56 + lane] = f0 * inv2;
        if (lane < 24) ob[56 + lane + 32] = f1 * inv2;
    } else if (w == 1) {
        if (lane == 0) {
            float me = fmaxf(s_oe[0], fmaxf(s_oe[1], s_oe[2]));
            float e0 = __expf(s_oe[0] - me), e1v = __expf(s_oe[1] - me), e2v = __expf(s_oe[2] - me);
            float inv = __fdividef(1.f, e0 + e1v + e2v);
            ob[112] = e0 * inv; ob[113] = e1v * inv; ob[114] = e2v * inv;
        } else if (lane == 1) {
            float mt = fmaxf(s_ot[0], s_ot[1]);
            float p0 = __expf(s_ot[0] - mt), p1 = __expf(s_ot[1] - mt);
            float invt = __fdividef(1.f, p0 + p1);
            ob[115] = p0 * invt; ob[116] = p1 * invt;
        } else if (lane == 2) {
            float acc = v3b[0];
            #pragma unroll
            for (int m = 0; m < 16; m++) acc += s_v2[m] * v3W[m];
            ob[117] = acc;
        }
    }
}

extern "C" void kernel_launch(void* const* d_in, const int* in_sizes, int n_in,
                              void* d_out, int out_size) {
    (void)in_sizes; (void)n_in; (void)out_size;
    policy_kernel<<<8192, NTHREADS>>>(
        (const int*)  d_in[0],  (const float*)d_in[1],
        (const float*)d_in[2],  (const float*)d_in[3],
        (const float*)d_in[4],  (const float*)d_in[5],
        (const float*)d_in[6],  (const float*)d_in[7],
        (const float*)d_in[8],  (const float*)d_in[9],
        (const float*)d_in[10], (const float*)d_in[11],
        (const float*)d_in[12], (const float*)d_in[13],
        (const float*)d_in[14], (const float*)d_in[15],
        (const float*)d_in[16], (const float*)d_in[17],
        (const float*)d_in[18], (const float*)d_in[19],
        (const float*)d_in[20], (const float*)d_in[21],
        (const float*)d_in[22], (const float*)d_in[23],
        (const float*)d_in[24], (const float*)d_in[25],
        (const float*)d_in[26], (const float*)d_in[27],
        (const float*)d_in[28], (const float*)d_in[29],
        (float*)d_out);
}